// round 9
// baseline (speedup 1.0000x reference)
#include <cuda_runtime.h>
#include <math.h>

// Problem constants (fixed by the reference)
#define BB   16384
#define KK   50
#define HH   64
#define REGC 0.01f
#define GRID 1024
#define UPB  16        // users per block: GRID*UPB == BB
#define STG  3         // pipeline stages (2 gather groups in flight)

// [0]=sum sq err, [1]=sum ||ie||, [2]=sum ||ue||
// Statically zero-init; last block re-zeroes after use (invariant per replay).
__device__ float    g_scratch[3];
__device__ unsigned g_count;

__device__ __forceinline__ void cpa16(void* s, const void* g) {
    unsigned sa = (unsigned)__cvta_generic_to_shared(s);
    asm volatile("cp.async.cg.shared.global [%0], [%1], 16;\n" :: "r"(sa), "l"(g));
}
__device__ __forceinline__ void cpa4(void* s, const void* g) {
    unsigned sa = (unsigned)__cvta_generic_to_shared(s);
    asm volatile("cp.async.ca.shared.global [%0], [%1], 4;\n" :: "r"(sa), "l"(g));
}

__global__ __launch_bounds__(128, 5) void mf_pipe_kernel(
    const float* __restrict__ uw,      // [100000,64]
    const float* __restrict__ iw,      // [1000000,64]
    const float* __restrict__ ub,      // [100000,1]
    const float* __restrict__ ib,      // [1000000,1]
    const float* __restrict__ bias,    // [1]
    const float* __restrict__ target,  // [B,K]
    const int*   __restrict__ user,    // [B]
    const int*   __restrict__ item,    // [B,K]
    float* __restrict__ out)           // [B*K + 1]
{
    __shared__ float rows_s[STG][KK][HH];   // 38.4 KB
    __shared__ float ue_s[STG][HH];
    __shared__ float tgt_s[STG][KK];
    __shared__ float ib_s[STG][KK];
    __shared__ int   itm_s[STG][KK];
    __shared__ int   usr_s[STG];
    __shared__ float ub_s[STG];
    __shared__ float pred_s[KK];
    __shared__ float ms_s[16], ns_s[16];

    const int tid  = threadIdx.x;
    const int warp = tid >> 5;
    const int lane = tid & 31;
    // Load-phase layout: half-warp per row (256B contiguous, conflict-free)
    const int half = (lane >> 4) & 1;
    const int hl   = lane & 15;
    const int hw   = warp * 2 + half;   // half-warp id 0..7
    // Compute-phase layout: 8 lanes per item
    const int slot = tid >> 3;          // 0..15 : item slot within round
    const int sub  = tid & 7;           // 0..7  : lane within item

    const int   b0    = blockIdx.x * UPB;
    const float gbias = bias[0];

    // ---- Prologue: indices for b0..b0+2, gather groups for b0, b0+1 ----
    if (tid < KK) {
        itm_s[0][tid] = item[(size_t)b0 * KK + tid];
        itm_s[1][tid] = item[(size_t)(b0 + 1) * KK + tid];
        itm_s[2][tid] = item[(size_t)(b0 + 2) * KK + tid];
    }
    if (tid == 0) {
        usr_s[0] = user[b0]; usr_s[1] = user[b0 + 1]; usr_s[2] = user[b0 + 2];
    }
    __syncthreads();

    #pragma unroll
    for (int s = 0; s < 2; ++s) {
        const int bs = b0 + s;
        const int us = usr_s[s];
        #pragma unroll
        for (int r = 0; r < 7; ++r) {
            const int k = r * 8 + hw;
            if (k < KK)
                cpa16(&rows_s[s][k][hl * 4], iw + (size_t)itm_s[s][k] * HH + hl * 4);
        }
        if (tid < 16) cpa16(&ue_s[s][tid * 4], uw + (size_t)us * HH + tid * 4);
        if (tid < KK) {
            cpa4(&ib_s[s][tid],  ib + itm_s[s][tid]);
            cpa4(&tgt_s[s][tid], target + (size_t)bs * KK + tid);
        }
        if (tid == 0) cpa4(&ub_s[s], ub + us);
        asm volatile("cp.async.commit_group;\n" ::: "memory");
    }

    float macc = 0.0f, nacc = 0.0f, uacc = 0.0f;

    #pragma unroll 1
    for (int i = 0; i < UPB; ++i) {
        const int b   = b0 + i;
        const int cur = i % STG;

        // Issue gather group for b+2 into its stage (indices already staged)
        if (i + 2 < UPB) {
            const int s2 = (i + 2) % STG;
            const int u2 = usr_s[s2];
            #pragma unroll
            for (int r = 0; r < 7; ++r) {
                const int k = r * 8 + hw;
                if (k < KK)
                    cpa16(&rows_s[s2][k][hl * 4], iw + (size_t)itm_s[s2][k] * HH + hl * 4);
            }
            if (tid < 16) cpa16(&ue_s[s2][tid * 4], uw + (size_t)u2 * HH + tid * 4);
            if (tid < KK) {
                cpa4(&ib_s[s2][tid],  ib + itm_s[s2][tid]);
                cpa4(&tgt_s[s2][tid], target + (size_t)(b + 2) * KK + tid);
            }
            if (tid == 0) cpa4(&ub_s[s2], ub + u2);
            asm volatile("cp.async.commit_group;\n" ::: "memory");
        }

        // Prefetch indices for b+3 to registers (latency hidden by compute)
        int my_itm = 0, my_usr = 0;
        if (i + 3 < UPB) {
            if (tid < KK) my_itm = item[(size_t)(b + 3) * KK + tid];
            if (tid == 0) my_usr = user[b + 3];
        }

        // Wait for group b: keep up to 2 newer groups in flight
        if      (i + 2 < UPB) asm volatile("cp.async.wait_group 2;\n" ::: "memory");
        else if (i + 1 < UPB) asm volatile("cp.async.wait_group 1;\n" ::: "memory");
        else                  asm volatile("cp.async.wait_group 0;\n" ::: "memory");
        __syncthreads();

        // Stage b+3 indices into slot cur (b's indices are dead; read by the
        // issue phase of iteration i+1, after this iteration's final barrier).
        if (i + 3 < UPB) {
            if (tid < KK) itm_s[cur][tid] = my_itm;
            if (tid == 0) usr_s[cur] = my_usr;
        }

        // ---- Compute user b from stage cur: 8 lanes per item ----
        const float ubv = ub_s[cur];
        float4 ua  = ((const float4*)ue_s[cur])[sub];
        float4 ub4 = ((const float4*)ue_s[cur])[sub + 8];
        ua.x += ubv; ua.y += ubv; ua.z += ubv; ua.w += ubv;
        ub4.x += ubv; ub4.y += ubv; ub4.z += ubv; ub4.w += ubv;

        if (warp == 0) {   // ||ue||: lanes 0-7 hold the full vector
            float usq = ua.x*ua.x + ua.y*ua.y + ua.z*ua.z + ua.w*ua.w
                      + ub4.x*ub4.x + ub4.y*ub4.y + ub4.z*ub4.z + ub4.w*ub4.w;
            #pragma unroll
            for (int m = 4; m >= 1; m >>= 1)
                usq += __shfl_xor_sync(0xffffffffu, usq, m);
            if (lane == 0) uacc += sqrtf(usq);
        }

        #pragma unroll
        for (int r = 0; r < 4; ++r) {
            const int k   = r * 16 + slot;
            const bool on = (k < KK);
            const int kc  = on ? k : (KK - 1);  // clamp: keep loads in-bounds

            const float bv = ib_s[cur][kc];
            const float4 wa = ((const float4*)rows_s[cur][kc])[sub];
            const float4 wb = ((const float4*)rows_s[cur][kc])[sub + 8];

            float4 ea, eb;
            ea.x = wa.x + bv; ea.y = wa.y + bv; ea.z = wa.z + bv; ea.w = wa.w + bv;
            eb.x = wb.x + bv; eb.y = wb.y + bv; eb.z = wb.z + bv; eb.w = wb.w + bv;

            float dot = ea.x*ua.x + ea.y*ua.y + ea.z*ua.z + ea.w*ua.w
                      + eb.x*ub4.x + eb.y*ub4.y + eb.z*ub4.z + eb.w*ub4.w;
            float sq  = ea.x*ea.x + ea.y*ea.y + ea.z*ea.z + ea.w*ea.w
                      + eb.x*eb.x + eb.y*eb.y + eb.z*eb.z + eb.w*eb.w;

            #pragma unroll
            for (int m = 4; m >= 1; m >>= 1) {
                dot += __shfl_xor_sync(0xffffffffu, dot, m);
                sq  += __shfl_xor_sync(0xffffffffu, sq,  m);
            }

            if (on && sub == 0) {
                const float pred = dot + gbias;
                pred_s[k] = pred;
                const float d = pred - tgt_s[cur][k];
                macc += d * d;
                nacc += sqrtf(sq);
            }
        }
        __syncthreads();   // pred_s complete; stage cur free; itm_s[cur] visible

        // Coalesced prediction store
        if (tid < KK) out[(size_t)b * KK + tid] = pred_s[tid];
    }

    // ---- Block reduce (16 leaders: tid%8==0) + global accumulate ----
    if (sub == 0) { ms_s[slot] = macc; ns_s[slot] = nacc; }
    __syncthreads();
    if (tid == 0) {
        float m = 0.0f, n = 0.0f;
        #pragma unroll
        for (int j = 0; j < 16; ++j) { m += ms_s[j]; n += ns_s[j]; }
        atomicAdd(&g_scratch[0], m);
        atomicAdd(&g_scratch[1], n);
        atomicAdd(&g_scratch[2], uacc);
        __threadfence();
        const unsigned t = atomicAdd(&g_count, 1u);
        if (t == (unsigned)(gridDim.x - 1)) {
            const float s0 = atomicAdd(&g_scratch[0], 0.0f);
            const float s1 = atomicAdd(&g_scratch[1], 0.0f);
            const float s2 = atomicAdd(&g_scratch[2], 0.0f);
            const float inv_bk = 1.0f / (float)((size_t)BB * KK);
            out[(size_t)BB * KK] = s0 * inv_bk
                                 + REGC * (s2 * (1.0f / (float)BB))
                                 + REGC * (s1 * inv_bk);
            g_scratch[0] = 0.0f; g_scratch[1] = 0.0f; g_scratch[2] = 0.0f;
            g_count = 0u;
        }
    }
}

extern "C" void kernel_launch(void* const* d_in, const int* in_sizes, int n_in,
                              void* d_out, int out_size) {
    const float* uw     = (const float*)d_in[0];
    const float* iw     = (const float*)d_in[1];
    const float* ub     = (const float*)d_in[2];
    const float* ib     = (const float*)d_in[3];
    const float* bias   = (const float*)d_in[4];
    const float* target = (const float*)d_in[5];
    const int*   user   = (const int*)d_in[6];
    const int*   item   = (const int*)d_in[7];
    float* out = (float*)d_out;

    mf_pipe_kernel<<<GRID, 128>>>(uw, iw, ub, ib, bias, target, user, item, out);
}

// round 11
// speedup vs baseline: 1.3961x; 1.3961x over previous
#include <cuda_runtime.h>
#include <math.h>

// Problem constants (fixed by the reference)
#define BB   16384
#define KK   50
#define HH   64
#define REGC 0.01f
#define GRID 1024
#define UPB  16        // users per block: GRID*UPB == BB

// [0]=sum sq err, [1]=sum ||ie||, [2]=sum ||ue||
// Statically zero-init; last block re-zeroes after use (invariant per replay).
__device__ float    g_scratch[3];
__device__ unsigned g_count;

__device__ __forceinline__ void cpa16(void* s, const void* g) {
    unsigned sa = (unsigned)__cvta_generic_to_shared(s);
    asm volatile("cp.async.cg.shared.global [%0], [%1], 16;\n" :: "r"(sa), "l"(g));
}
__device__ __forceinline__ void cpa4(void* s, const void* g) {
    unsigned sa = (unsigned)__cvta_generic_to_shared(s);
    asm volatile("cp.async.ca.shared.global [%0], [%1], 4;\n" :: "r"(sa), "l"(g));
}
__device__ __forceinline__ void pf_l2(const void* g) {
    asm volatile("prefetch.global.L2 [%0];" :: "l"(g));
}

__global__ __launch_bounds__(128, 8) void mf_pipe_kernel(
    const float* __restrict__ uw,      // [100000,64]
    const float* __restrict__ iw,      // [1000000,64]
    const float* __restrict__ ub,      // [100000,1]
    const float* __restrict__ ib,      // [1000000,1]
    const float* __restrict__ bias,    // [1]
    const float* __restrict__ target,  // [B,K]
    const int*   __restrict__ user,    // [B]
    const int*   __restrict__ item,    // [B,K]
    float* __restrict__ out)           // [B*K + 1]
{
    __shared__ float rows_s[2][KK][HH];   // 25.6 KB
    __shared__ float ue_s[2][HH];
    __shared__ float tgt_s[2][KK];
    __shared__ float ib_s[2][KK];
    __shared__ int   itm_s[2][KK];
    __shared__ int   usr_s[2];
    __shared__ float ub_s[2];
    __shared__ float pred_s[KK];
    __shared__ float ms_s[16], ns_s[16];

    const int tid  = threadIdx.x;
    const int warp = tid >> 5;
    const int lane = tid & 31;
    // Load-phase layout: half-warp per row (256B contiguous, conflict-free)
    const int half = (lane >> 4) & 1;
    const int hl   = lane & 15;
    const int hw   = warp * 2 + half;   // half-warp id 0..7
    // Compute-phase layout: 8 lanes per item
    const int slot = tid >> 3;          // 0..15 : item slot within round
    const int sub  = tid & 7;           // 0..7  : lane within item

    const int   b0    = blockIdx.x * UPB;
    const float gbias = bias[0];

    // ---- Prologue: indices for b0 (stage 0) and b0+1 (stage 1) ----
    if (tid < KK) {
        itm_s[0][tid] = item[b0 * KK + tid];
        itm_s[1][tid] = item[(b0 + 1) * KK + tid];
    }
    if (tid == 0) { usr_s[0] = user[b0]; usr_s[1] = user[b0 + 1]; }
    __syncthreads();

    // Issue group for b0 into stage 0
    {
        const int u0 = usr_s[0];
        #pragma unroll
        for (int r = 0; r < 7; ++r) {
            const int k = r * 8 + hw;
            if (k < KK)
                cpa16(&rows_s[0][k][hl * 4], iw + (size_t)itm_s[0][k] * HH + hl * 4);
        }
        if (tid < 16) cpa16(&ue_s[0][tid * 4], uw + (size_t)u0 * HH + tid * 4);
        if (tid < KK) {
            cpa4(&ib_s[0][tid],  ib + itm_s[0][tid]);
            cpa4(&tgt_s[0][tid], target + (size_t)b0 * KK + tid);
        }
        if (tid == 0) cpa4(&ub_s[0], ub + u0);
        asm volatile("cp.async.commit_group;\n" ::: "memory");
    }

    float macc = 0.0f, nacc = 0.0f, uacc = 0.0f;

    #pragma unroll 1
    for (int i = 0; i < UPB; ++i) {
        const int b   = b0 + i;
        const int cur = i & 1;
        const int nxt = cur ^ 1;

        // Issue group for b+1 into stage nxt (indices already staged; rows were
        // L2-prefetched one iteration ago -> short-latency fill)
        if (i + 1 < UPB) {
            const int un = usr_s[nxt];
            #pragma unroll
            for (int r = 0; r < 7; ++r) {
                const int k = r * 8 + hw;
                if (k < KK)
                    cpa16(&rows_s[nxt][k][hl * 4], iw + (size_t)itm_s[nxt][k] * HH + hl * 4);
            }
            if (tid < 16) cpa16(&ue_s[nxt][tid * 4], uw + (size_t)un * HH + tid * 4);
            if (tid < KK) {
                cpa4(&ib_s[nxt][tid],  ib + itm_s[nxt][tid]);
                cpa4(&tgt_s[nxt][tid], target + (size_t)(b + 1) * KK + tid);
            }
            if (tid == 0) cpa4(&ub_s[nxt], ub + un);
            asm volatile("cp.async.commit_group;\n" ::: "memory");
        }

        // Kick off index loads for b+2 (latency hidden by compute below)
        int my_itm = 0, my_usr = 0;
        if (i + 2 < UPB) {
            if (tid < KK) my_itm = item[(size_t)(b + 2) * KK + tid];
            if (tid == 0) my_usr = user[b + 2];
        }

        if (i + 1 < UPB) asm volatile("cp.async.wait_group 1;\n" ::: "memory");
        else             asm volatile("cp.async.wait_group 0;\n" ::: "memory");
        __syncthreads();

        // Stage indices for b+2 into the freed slot, and L2-prefetch b+2's
        // rows NOW: by the time they are cp.async'd (next iteration) and
        // consumed (iteration after), DRAM latency is already paid.
        if (i + 2 < UPB) {
            if (tid < KK) {
                itm_s[cur][tid] = my_itm;
                const char* p = (const char*)(iw + (size_t)my_itm * HH);
                pf_l2(p);
                pf_l2(p + 128);
            }
            if (tid == 0) usr_s[cur] = my_usr;
        }

        // ---- Compute user b from stage cur: 8 lanes per item ----
        const float ubv = ub_s[cur];
        float4 ua  = ((const float4*)ue_s[cur])[sub];
        float4 ub4 = ((const float4*)ue_s[cur])[sub + 8];
        ua.x += ubv; ua.y += ubv; ua.z += ubv; ua.w += ubv;
        ub4.x += ubv; ub4.y += ubv; ub4.z += ubv; ub4.w += ubv;

        if (warp == 0) {   // ||ue||: lanes 0-7 hold the full vector
            float usq = ua.x*ua.x + ua.y*ua.y + ua.z*ua.z + ua.w*ua.w
                      + ub4.x*ub4.x + ub4.y*ub4.y + ub4.z*ub4.z + ub4.w*ub4.w;
            #pragma unroll
            for (int m = 4; m >= 1; m >>= 1)
                usq += __shfl_xor_sync(0xffffffffu, usq, m);
            if (lane == 0) uacc += sqrtf(usq);
        }

        #pragma unroll
        for (int r = 0; r < 4; ++r) {
            const int k   = r * 16 + slot;
            const bool on = (k < KK);
            const int kc  = on ? k : (KK - 1);  // clamp: keep loads in-bounds

            const float bv = ib_s[cur][kc];
            const float4 wa = ((const float4*)rows_s[cur][kc])[sub];
            const float4 wb = ((const float4*)rows_s[cur][kc])[sub + 8];

            float4 ea, eb;
            ea.x = wa.x + bv; ea.y = wa.y + bv; ea.z = wa.z + bv; ea.w = wa.w + bv;
            eb.x = wb.x + bv; eb.y = wb.y + bv; eb.z = wb.z + bv; eb.w = wb.w + bv;

            float dot = ea.x*ua.x + ea.y*ua.y + ea.z*ua.z + ea.w*ua.w
                      + eb.x*ub4.x + eb.y*ub4.y + eb.z*ub4.z + eb.w*ub4.w;
            float sq  = ea.x*ea.x + ea.y*ea.y + ea.z*ea.z + ea.w*ea.w
                      + eb.x*eb.x + eb.y*eb.y + eb.z*eb.z + eb.w*eb.w;

            #pragma unroll
            for (int m = 4; m >= 1; m >>= 1) {
                dot += __shfl_xor_sync(0xffffffffu, dot, m);
                sq  += __shfl_xor_sync(0xffffffffu, sq,  m);
            }

            if (on && sub == 0) {
                const float pred = dot + gbias;
                pred_s[k] = pred;
                const float d = pred - tgt_s[cur][k];
                macc += d * d;
                nacc += sqrtf(sq);
            }
        }
        __syncthreads();   // pred_s complete; stage cur free; itm_s[cur] visible

        // Coalesced prediction store
        if (tid < KK) out[(size_t)b * KK + tid] = pred_s[tid];
    }

    // ---- Block reduce (16 leaders: tid%8==0) + global accumulate ----
    if (sub == 0) { ms_s[slot] = macc; ns_s[slot] = nacc; }
    __syncthreads();
    if (tid == 0) {
        float m = 0.0f, n = 0.0f;
        #pragma unroll
        for (int j = 0; j < 16; ++j) { m += ms_s[j]; n += ns_s[j]; }
        atomicAdd(&g_scratch[0], m);
        atomicAdd(&g_scratch[1], n);
        atomicAdd(&g_scratch[2], uacc);
        __threadfence();
        const unsigned t = atomicAdd(&g_count, 1u);
        if (t == (unsigned)(gridDim.x - 1)) {
            const float s0 = atomicAdd(&g_scratch[0], 0.0f);
            const float s1 = atomicAdd(&g_scratch[1], 0.0f);
            const float s2 = atomicAdd(&g_scratch[2], 0.0f);
            const float inv_bk = 1.0f / (float)((size_t)BB * KK);
            out[(size_t)BB * KK] = s0 * inv_bk
                                 + REGC * (s2 * (1.0f / (float)BB))
                                 + REGC * (s1 * inv_bk);
            g_scratch[0] = 0.0f; g_scratch[1] = 0.0f; g_scratch[2] = 0.0f;
            g_count = 0u;
        }
    }
}

extern "C" void kernel_launch(void* const* d_in, const int* in_sizes, int n_in,
                              void* d_out, int out_size) {
    const float* uw     = (const float*)d_in[0];
    const float* iw     = (const float*)d_in[1];
    const float* ub     = (const float*)d_in[2];
    const float* ib     = (const float*)d_in[3];
    const float* bias   = (const float*)d_in[4];
    const float* target = (const float*)d_in[5];
    const int*   user   = (const int*)d_in[6];
    const int*   item   = (const int*)d_in[7];
    float* out = (float*)d_out;

    mf_pipe_kernel<<<GRID, 128>>>(uw, iw, ub, ib, bias, target, user, item, out);
}